// round 10
// baseline (speedup 1.0000x reference)
#include <cuda_runtime.h>

#define NN 50000
#define EE 800000
#define ET 850000   // EE + NN self-loops
#define SB 512      // scan block size
#define NB ((NN + SB - 1) / SB)   // 98 scan blocks

// ---------------- scratch (device globals; no runtime allocation) ----------
__device__ int   g_deg[NN];
__device__ int   g_cur[NN];
__device__ int   g_off[NN + 1];
__device__ float g_dis[NN];
__device__ int   g_part[NB];
__device__ int   g_pscan[NB];
__device__ int   g_src[ET];
__device__ float g_w[ET];
__device__ float g_bufA[(size_t)NN * 128];
__device__ float g_bufB[(size_t)NN * 128];

// Compile-time buffer selector (no host-side symbol lookup).
enum Which { A_, B_, X_ };
template <Which W>
__device__ __forceinline__ const float* inbuf(const float* ext) {
    if constexpr (W == A_) return g_bufA;
    else if constexpr (W == B_) return g_bufB;
    else return ext;
}
template <Which W>
__device__ __forceinline__ float* outbuf(float* ext) {
    if constexpr (W == A_) return g_bufA;
    else if constexpr (W == B_) return g_bufB;
    else return ext;
}

// ---------------- graph prep ------------------------------------------------
__global__ void k_zero() {
    int i = blockIdx.x * blockDim.x + threadIdx.x;
    if (i < NN) { g_deg[i] = 0; g_cur[i] = 0; }
}

// edge_index is int32 (JAX x64 disabled). Count-only pass (no edge copy-out).
__global__ void k_count(const int* __restrict__ ei) {
    int e = blockIdx.x * blockDim.x + threadIdx.x;
    if (e >= EE) return;
    int c = ei[EE + e];
    if ((unsigned)c >= NN) c = 0;   // never trap on bad data
    atomicAdd(&g_deg[c], 1);
}

// phase 1: per-block sums of (deg[i]+1)
__global__ __launch_bounds__(SB) void k_scan1() {
    __shared__ int s[SB];
    int t = threadIdx.x;
    int i = blockIdx.x * SB + t;
    s[t] = (i < NN) ? (g_deg[i] + 1) : 0;
    __syncthreads();
#pragma unroll
    for (int o = SB / 2; o > 0; o >>= 1) {
        if (t < o) s[t] += s[t + o];
        __syncthreads();
    }
    if (t == 0) g_part[blockIdx.x] = s[0];
}

// phase 2: exclusive scan of the NB partials (single block of 128)
__global__ __launch_bounds__(128) void k_scan2() {
    __shared__ int s[128];
    int t = threadIdx.x;
    int v = (t < NB) ? g_part[t] : 0;
    s[t] = v;
    __syncthreads();
#pragma unroll
    for (int o = 1; o < 128; o <<= 1) {
        int u = (t >= o) ? s[t - o] : 0;
        __syncthreads();
        s[t] += u;
        __syncthreads();
    }
    if (t < NB) g_pscan[t] = s[t] - v;
    if (t == 0) g_off[NN] = ET;   // total is a compile-time constant
}

// phase 3: block-local exclusive scan + base, write g_off and g_dis
__global__ __launch_bounds__(SB) void k_scan3() {
    __shared__ int s[SB];
    int t = threadIdx.x;
    int i = blockIdx.x * SB + t;
    int d = (i < NN) ? g_deg[i] : 0;
    int v = (i < NN) ? (d + 1) : 0;
    s[t] = v;
    __syncthreads();
#pragma unroll
    for (int o = 1; o < SB; o <<= 1) {
        int u = (t >= o) ? s[t - o] : 0;
        __syncthreads();
        s[t] += u;
        __syncthreads();
    }
    if (i < NN) {
        g_off[i] = g_pscan[blockIdx.x] + s[t] - v;
        g_dis[i] = rsqrtf((float)(d + 1));
    }
}

// fill CSR: edges (re-read ei directly) + self loops in one kernel
__global__ void k_fillself(const int* __restrict__ ei) {
    int e = blockIdx.x * blockDim.x + threadIdx.x;
    if (e < EE) {
        int r = ei[e];
        int c = ei[EE + e];
        if ((unsigned)r >= NN) r = 0;
        if ((unsigned)c >= NN) c = 0;
        int p = atomicAdd(&g_cur[c], 1);
        int idx = g_off[c] + p;
        g_src[idx] = r;
        g_w[idx] = g_dis[r] * g_dis[c];
    } else if (e < EE + NN) {
        int n = e - EE;
        int idx = g_off[n + 1] - 1;   // last slot of each segment
        g_src[idx] = n;
        float d = g_dis[n];
        g_w[idx] = d * d;
    }
}

// ---------------- scalar aggregation (F not divisible by 4: F=29) ----------
template <int F, bool BIAS, Which SRC, Which DST>
__global__ __launch_bounds__(256) void k_agg(const float* __restrict__ ext_in,
                                             const float* __restrict__ b,
                                             float* __restrict__ ext_out) {
    const float* __restrict__ h = inbuf<SRC>(ext_in);
    float* __restrict__ out = outbuf<DST>(ext_out);
    constexpr int NACC = (F + 31) / 32;
    int warp = (blockIdx.x * blockDim.x + threadIdx.x) >> 5;
    int lane = threadIdx.x & 31;
    if (warp >= NN) return;
    int n = warp;
    int s = g_off[n], e = g_off[n + 1];
    float acc[NACC];
#pragma unroll
    for (int j = 0; j < NACC; j++) acc[j] = 0.f;
    for (int i = s; i < e; i++) {
        int src = g_src[i];
        float w = g_w[i];
        const float* hp = h + (size_t)src * F;
#pragma unroll
        for (int j = 0; j < NACC; j++) {
            int f = lane + 32 * j;
            if (f < F) acc[j] += w * __ldg(hp + f);
        }
    }
    float* op = out + (size_t)n * F;
#pragma unroll
    for (int j = 0; j < NACC; j++) {
        int f = lane + 32 * j;
        if (f < F) op[f] = acc[j] + (BIAS ? b[f] : 0.f);
    }
}

// ---------------- vectorized aggregation (F % 4 == 0) -----------------------
template <int F, bool BIAS, Which SRC, Which DST>
__global__ __launch_bounds__(256) void k_agg4(const float* __restrict__ ext_in,
                                              const float* __restrict__ b,
                                              float* __restrict__ ext_out) {
    static_assert(F % 4 == 0, "F must be divisible by 4");
    constexpr int L = F / 4;     // lanes per edge
    constexpr int G = 32 / L;    // concurrent edges per warp
    const float* __restrict__ h = inbuf<SRC>(ext_in);
    float* __restrict__ out = outbuf<DST>(ext_out);
    int warp = (blockIdx.x * blockDim.x + threadIdx.x) >> 5;
    int lane = threadIdx.x & 31;
    if (warp >= NN) return;
    int g = lane / L;
    int q = lane - g * L;
    int s = g_off[warp], e = g_off[warp + 1];
    float4 acc = make_float4(0.f, 0.f, 0.f, 0.f);
    if (g < G) {
        for (int i = s + g; i < e; i += G) {
            int   src = g_src[i];
            float w   = g_w[i];
            float4 v = __ldg((const float4*)(h + (size_t)src * F) + q);
            acc.x += w * v.x; acc.y += w * v.y;
            acc.z += w * v.z; acc.w += w * v.w;
        }
    }
#pragma unroll
    for (int st = G / 2; st >= 1; st >>= 1) {
        int off = st * L;
        acc.x += __shfl_xor_sync(0xffffffffu, acc.x, off);
        acc.y += __shfl_xor_sync(0xffffffffu, acc.y, off);
        acc.z += __shfl_xor_sync(0xffffffffu, acc.z, off);
        acc.w += __shfl_xor_sync(0xffffffffu, acc.w, off);
    }
    if (g == 0) {
        if (BIAS) {
            float4 bb = __ldg((const float4*)b + q);
            acc.x += bb.x; acc.y += bb.y; acc.z += bb.z; acc.w += bb.w;
        }
        ((float4*)(out + (size_t)warp * F))[q] = acc;
    }
}

// ---------------- tiled GEMM: out[n][o] = bias + sum_k x[n][k]*W[k][o] ------
// 64-node x TN-output tile per 256-thread block; W slice loaded once per
// block. Weight inner loads vectorized (float4 for VN=4, float2 for VN=2).
template <int IN, int OUT, int NOB, bool BIAS, bool RELU, Which SRC, Which DST>
__global__ __launch_bounds__(256) void k_gemm_t(const float* __restrict__ ext_in,
                                                const float* __restrict__ W,
                                                const float* __restrict__ b,
                                                float* __restrict__ ext_out) {
    constexpr int TN  = OUT / NOB;                 // 48, 64, 64, 32
    constexpr int VN  = TN / 16;                   // 3, 4, 4, 2
    constexpr int KT  = 16;
    constexpr int INP = ((IN + KT - 1) / KT) * KT; // 32, 96, 128, 64
    const float* __restrict__ x = inbuf<SRC>(ext_in);
    float* __restrict__ out = outbuf<DST>(ext_out);

    __shared__ float Xs[KT][64];
    __shared__ float Wsm[INP][TN];

    int t  = threadIdx.x;
    int tx = t & 15, ty = t >> 4;
    int mB = blockIdx.x * 64;
    int oB = blockIdx.y * TN;

    // load W slice into shared (zero-pad k >= IN)
    for (int i = t; i < INP * TN; i += 256) {
        int k = i / TN, o = i % TN;
        Wsm[k][o] = (k < IN) ? W[k * OUT + oB + o] : 0.f;
    }

    float acc[4][VN];
#pragma unroll
    for (int i = 0; i < 4; i++)
#pragma unroll
        for (int j = 0; j < VN; j++) acc[i][j] = 0.f;

    int mLoad = t >> 2;            // 0..63: node this thread stages
    int c4    = (t & 3) * 4;       // k-offset within tile
    const float* xrow = x + (size_t)(mB + mLoad) * IN;
    bool mvalid = (mB + mLoad) < NN;

    for (int kb = 0; kb < INP; kb += KT) {
        float4 v = make_float4(0.f, 0.f, 0.f, 0.f);
        if (mvalid) {
            int k0 = kb + c4;
            if constexpr (IN % 4 == 0) {
                v = *(const float4*)(xrow + k0);   // rows 16B-aligned
            } else {
                if (k0 + 0 < IN) v.x = xrow[k0 + 0];
                if (k0 + 1 < IN) v.y = xrow[k0 + 1];
                if (k0 + 2 < IN) v.z = xrow[k0 + 2];
                if (k0 + 3 < IN) v.w = xrow[k0 + 3];
            }
        }
        __syncthreads();           // previous tile fully consumed (also orders Wsm)
        Xs[c4 + 0][mLoad] = v.x;
        Xs[c4 + 1][mLoad] = v.y;
        Xs[c4 + 2][mLoad] = v.z;
        Xs[c4 + 3][mLoad] = v.w;
        __syncthreads();
#pragma unroll
        for (int kk = 0; kk < KT; kk++) {
            float4 xv = *(const float4*)&Xs[kk][ty * 4];
            float wv[VN];
            if constexpr (VN == 4) {
                float4 wq = *(const float4*)&Wsm[kb + kk][tx * 4];
                wv[0] = wq.x; wv[1] = wq.y; wv[2] = wq.z; wv[3] = wq.w;
            } else if constexpr (VN == 2) {
                float2 wd = *(const float2*)&Wsm[kb + kk][tx * 2];
                wv[0] = wd.x; wv[1] = wd.y;
            } else {
#pragma unroll
                for (int j = 0; j < VN; j++) wv[j] = Wsm[kb + kk][tx * VN + j];
            }
#pragma unroll
            for (int j = 0; j < VN; j++) {
                acc[0][j] += xv.x * wv[j];
                acc[1][j] += xv.y * wv[j];
                acc[2][j] += xv.z * wv[j];
                acc[3][j] += xv.w * wv[j];
            }
        }
    }

#pragma unroll
    for (int i = 0; i < 4; i++) {
        int m = mB + ty * 4 + i;
        if (m < NN) {
#pragma unroll
            for (int j = 0; j < VN; j++) {
                int o = oB + tx * VN + j;
                float vv = acc[i][j] + (BIAS ? __ldg(b + o) : 0.f);
                out[(size_t)m * OUT + o] = RELU ? fmaxf(vv, 0.f) : vv;
            }
        }
    }
}

// ---------------- launch ----------------------------------------------------
static inline int ceil_div(int a, int b) { return (a + b - 1) / b; }

extern "C" void kernel_launch(void* const* d_in, const int* in_sizes, int n_in,
                              void* d_out, int out_size) {
    const float* x  = (const float*)d_in[0];
    const int*   ei = (const int*)d_in[1];   // int32 edge_index (2, E)
    const float* W1 = (const float*)d_in[2]; const float* b1 = (const float*)d_in[3];
    const float* W2 = (const float*)d_in[4]; const float* b2 = (const float*)d_in[5];
    const float* W3 = (const float*)d_in[6]; const float* b3 = (const float*)d_in[7];
    const float* W4 = (const float*)d_in[8]; const float* b4 = (const float*)d_in[9];
    float* out = (float*)d_out;

    const int TB = 256;
    const int gN  = ceil_div(NN, TB);
    const int gE  = ceil_div(EE, TB);
    const int gET = ceil_div(ET, TB);
    const int gW  = ceil_div(NN, TB / 32);   // one warp per node
    const int gM  = ceil_div(NN, 64);        // gemm node-blocks (782)

    // graph prep
    k_zero<<<gN, TB>>>();
    k_count<<<gE, TB>>>(ei);
    k_scan1<<<NB, SB>>>();
    k_scan2<<<1, 128>>>();
    k_scan3<<<NB, SB>>>();
    k_fillself<<<gET, TB>>>(ei);

    // layer 1: h1 = relu((A x) W1 + b1)   — aggregate 29 feats, then GEMM
    k_agg<29, false, X_, A_><<<gW, TB>>>(x, nullptr, nullptr);
    k_gemm_t<29, 96, 2, true, true, A_, B_><<<dim3(gM, 2), TB>>>(nullptr, W1, b1, nullptr);

    // layer 2: h2 = (A h1) W2 + b2       — aggregate 96 feats, then GEMM
    k_agg4<96, false, B_, A_><<<gW, TB>>>(nullptr, nullptr, nullptr);
    k_gemm_t<96, 128, 2, true, false, A_, B_><<<dim3(gM, 2), TB>>>(nullptr, W2, b2, nullptr);

    // layer 3: h3 = A (h2 W3) + b3       — GEMM first (64 < 128), agg with bias
    k_gemm_t<128, 64, 1, false, false, B_, A_><<<dim3(gM, 1), TB>>>(nullptr, W3, nullptr, nullptr);
    k_agg4<64, true, A_, B_><<<gW, TB>>>(nullptr, b3, nullptr);

    // layer 4: out = A (h3 W4) + b4      — GEMM first (32 < 64), agg with bias
    k_gemm_t<64, 32, 1, false, false, B_, A_><<<dim3(gM, 1), TB>>>(nullptr, W4, nullptr, nullptr);
    k_agg4<32, true, A_, X_><<<gW, TB>>>(nullptr, b4, out);

    (void)in_sizes; (void)n_in; (void)out_size;
}

// round 11
// speedup vs baseline: 1.0498x; 1.0498x over previous
#include <cuda_runtime.h>

#define NN 50000
#define EE 800000
#define ET 850000   // EE + NN self-loops
#define SB 512      // scan block size
#define NB ((NN + SB - 1) / SB)   // 98 scan blocks

// ---------------- scratch (device globals; no runtime allocation) ----------
__device__ int   g_deg[NN];
__device__ int   g_cur[NN];
__device__ int   g_off[NN + 1];
__device__ float g_dis[NN];
__device__ int   g_part[NB];
__device__ int   g_pscan[NB];
__device__ int   g_src[ET];
__device__ float g_w[ET];
__device__ float g_bufA[(size_t)NN * 128];
__device__ float g_bufB[(size_t)NN * 128];

// Compile-time buffer selector (no host-side symbol lookup).
enum Which { A_, B_, X_ };
template <Which W>
__device__ __forceinline__ const float* inbuf(const float* ext) {
    if constexpr (W == A_) return g_bufA;
    else if constexpr (W == B_) return g_bufB;
    else return ext;
}
template <Which W>
__device__ __forceinline__ float* outbuf(float* ext) {
    if constexpr (W == A_) return g_bufA;
    else if constexpr (W == B_) return g_bufB;
    else return ext;
}

// ---------------- graph prep ------------------------------------------------
__global__ void k_zero() {
    int i = blockIdx.x * blockDim.x + threadIdx.x;
    if (i < NN) { g_deg[i] = 0; g_cur[i] = 0; }
}

// edge_index is int32 (JAX x64 disabled). Count-only pass (no edge copy-out).
__global__ void k_count(const int* __restrict__ ei) {
    int e = blockIdx.x * blockDim.x + threadIdx.x;
    if (e >= EE) return;
    int c = ei[EE + e];
    if ((unsigned)c >= NN) c = 0;   // never trap on bad data
    atomicAdd(&g_deg[c], 1);
}

// phase 1: per-block sums of (deg[i]+1)
__global__ __launch_bounds__(SB) void k_scan1() {
    __shared__ int s[SB];
    int t = threadIdx.x;
    int i = blockIdx.x * SB + t;
    s[t] = (i < NN) ? (g_deg[i] + 1) : 0;
    __syncthreads();
#pragma unroll
    for (int o = SB / 2; o > 0; o >>= 1) {
        if (t < o) s[t] += s[t + o];
        __syncthreads();
    }
    if (t == 0) g_part[blockIdx.x] = s[0];
}

// phase 2: exclusive scan of the NB partials (single block of 128)
__global__ __launch_bounds__(128) void k_scan2() {
    __shared__ int s[128];
    int t = threadIdx.x;
    int v = (t < NB) ? g_part[t] : 0;
    s[t] = v;
    __syncthreads();
#pragma unroll
    for (int o = 1; o < 128; o <<= 1) {
        int u = (t >= o) ? s[t - o] : 0;
        __syncthreads();
        s[t] += u;
        __syncthreads();
    }
    if (t < NB) g_pscan[t] = s[t] - v;
    if (t == 0) g_off[NN] = ET;   // total is a compile-time constant
}

// phase 3: block-local exclusive scan + base, write g_off and g_dis
__global__ __launch_bounds__(SB) void k_scan3() {
    __shared__ int s[SB];
    int t = threadIdx.x;
    int i = blockIdx.x * SB + t;
    int d = (i < NN) ? g_deg[i] : 0;
    int v = (i < NN) ? (d + 1) : 0;
    s[t] = v;
    __syncthreads();
#pragma unroll
    for (int o = 1; o < SB; o <<= 1) {
        int u = (t >= o) ? s[t - o] : 0;
        __syncthreads();
        s[t] += u;
        __syncthreads();
    }
    if (i < NN) {
        g_off[i] = g_pscan[blockIdx.x] + s[t] - v;
        g_dis[i] = rsqrtf((float)(d + 1));
    }
}

// fill CSR: edges (re-read ei directly) + self loops in one kernel
__global__ void k_fillself(const int* __restrict__ ei) {
    int e = blockIdx.x * blockDim.x + threadIdx.x;
    if (e < EE) {
        int r = ei[e];
        int c = ei[EE + e];
        if ((unsigned)r >= NN) r = 0;
        if ((unsigned)c >= NN) c = 0;
        int p = atomicAdd(&g_cur[c], 1);
        int idx = g_off[c] + p;
        g_src[idx] = r;
        g_w[idx] = g_dis[r] * g_dis[c];
    } else if (e < EE + NN) {
        int n = e - EE;
        int idx = g_off[n + 1] - 1;   // last slot of each segment
        g_src[idx] = n;
        float d = g_dis[n];
        g_w[idx] = d * d;
    }
}

// ---------------- scalar aggregation (F not divisible by 4: F=29) ----------
template <int F, bool BIAS, Which SRC, Which DST>
__global__ __launch_bounds__(256) void k_agg(const float* __restrict__ ext_in,
                                             const float* __restrict__ b,
                                             float* __restrict__ ext_out) {
    const float* __restrict__ h = inbuf<SRC>(ext_in);
    float* __restrict__ out = outbuf<DST>(ext_out);
    constexpr int NACC = (F + 31) / 32;
    int warp = (blockIdx.x * blockDim.x + threadIdx.x) >> 5;
    int lane = threadIdx.x & 31;
    if (warp >= NN) return;
    int n = warp;
    int s = g_off[n], e = g_off[n + 1];
    float acc[NACC];
#pragma unroll
    for (int j = 0; j < NACC; j++) acc[j] = 0.f;
    for (int i = s; i < e; i++) {
        int src = g_src[i];
        float w = g_w[i];
        const float* hp = h + (size_t)src * F;
#pragma unroll
        for (int j = 0; j < NACC; j++) {
            int f = lane + 32 * j;
            if (f < F) acc[j] += w * __ldg(hp + f);
        }
    }
    float* op = out + (size_t)n * F;
#pragma unroll
    for (int j = 0; j < NACC; j++) {
        int f = lane + 32 * j;
        if (f < F) op[f] = acc[j] + (BIAS ? b[f] : 0.f);
    }
}

// ---------------- vectorized aggregation (F % 4 == 0) -----------------------
template <int F, bool BIAS, Which SRC, Which DST>
__global__ __launch_bounds__(256) void k_agg4(const float* __restrict__ ext_in,
                                              const float* __restrict__ b,
                                              float* __restrict__ ext_out) {
    static_assert(F % 4 == 0, "F must be divisible by 4");
    constexpr int L = F / 4;     // lanes per edge
    constexpr int G = 32 / L;    // concurrent edges per warp
    const float* __restrict__ h = inbuf<SRC>(ext_in);
    float* __restrict__ out = outbuf<DST>(ext_out);
    int warp = (blockIdx.x * blockDim.x + threadIdx.x) >> 5;
    int lane = threadIdx.x & 31;
    if (warp >= NN) return;
    int g = lane / L;
    int q = lane - g * L;
    int s = g_off[warp], e = g_off[warp + 1];
    float4 acc = make_float4(0.f, 0.f, 0.f, 0.f);
    if (g < G) {
        for (int i = s + g; i < e; i += G) {
            int   src = g_src[i];
            float w   = g_w[i];
            float4 v = __ldg((const float4*)(h + (size_t)src * F) + q);
            acc.x += w * v.x; acc.y += w * v.y;
            acc.z += w * v.z; acc.w += w * v.w;
        }
    }
#pragma unroll
    for (int st = G / 2; st >= 1; st >>= 1) {
        int off = st * L;
        acc.x += __shfl_xor_sync(0xffffffffu, acc.x, off);
        acc.y += __shfl_xor_sync(0xffffffffu, acc.y, off);
        acc.z += __shfl_xor_sync(0xffffffffu, acc.z, off);
        acc.w += __shfl_xor_sync(0xffffffffu, acc.w, off);
    }
    if (g == 0) {
        if (BIAS) {
            float4 bb = __ldg((const float4*)b + q);
            acc.x += bb.x; acc.y += bb.y; acc.z += bb.z; acc.w += bb.w;
        }
        ((float4*)(out + (size_t)warp * F))[q] = acc;
    }
}

// ---------------- tiled GEMM: out[n][o] = bias + sum_k x[n][k]*W[k][o] ------
// 64-node x TN-output tile per 256-thread block; W slice loaded once per
// block. Weight inner loads SCALAR (R9 known-good — ptxas interleaves the
// 4 scalar LDS into the FFMA stream; LDS.128 here regressed, R10).
template <int IN, int OUT, int NOB, bool BIAS, bool RELU, Which SRC, Which DST>
__global__ __launch_bounds__(256) void k_gemm_t(const float* __restrict__ ext_in,
                                                const float* __restrict__ W,
                                                const float* __restrict__ b,
                                                float* __restrict__ ext_out) {
    constexpr int TN  = OUT / NOB;                 // 48, 64, 64, 32
    constexpr int VN  = TN / 16;                   // 3, 4, 4, 2
    constexpr int KT  = 16;
    constexpr int INP = ((IN + KT - 1) / KT) * KT; // 32, 96, 128, 64
    const float* __restrict__ x = inbuf<SRC>(ext_in);
    float* __restrict__ out = outbuf<DST>(ext_out);

    __shared__ float Xs[KT][64];
    __shared__ float Wsm[INP][TN];

    int t  = threadIdx.x;
    int tx = t & 15, ty = t >> 4;
    int mB = blockIdx.x * 64;
    int oB = blockIdx.y * TN;

    // load W slice into shared (zero-pad k >= IN)
    for (int i = t; i < INP * TN; i += 256) {
        int k = i / TN, o = i % TN;
        Wsm[k][o] = (k < IN) ? W[k * OUT + oB + o] : 0.f;
    }

    float acc[4][VN];
#pragma unroll
    for (int i = 0; i < 4; i++)
#pragma unroll
        for (int j = 0; j < VN; j++) acc[i][j] = 0.f;

    int mLoad = t >> 2;            // 0..63: node this thread stages
    int c4    = (t & 3) * 4;       // k-offset within tile
    const float* xrow = x + (size_t)(mB + mLoad) * IN;
    bool mvalid = (mB + mLoad) < NN;

    for (int kb = 0; kb < INP; kb += KT) {
        float4 v = make_float4(0.f, 0.f, 0.f, 0.f);
        if (mvalid) {
            int k0 = kb + c4;
            if constexpr (IN % 4 == 0) {
                v = *(const float4*)(xrow + k0);   // rows 16B-aligned
            } else {
                if (k0 + 0 < IN) v.x = xrow[k0 + 0];
                if (k0 + 1 < IN) v.y = xrow[k0 + 1];
                if (k0 + 2 < IN) v.z = xrow[k0 + 2];
                if (k0 + 3 < IN) v.w = xrow[k0 + 3];
            }
        }
        __syncthreads();           // previous tile fully consumed (also orders Wsm)
        Xs[c4 + 0][mLoad] = v.x;
        Xs[c4 + 1][mLoad] = v.y;
        Xs[c4 + 2][mLoad] = v.z;
        Xs[c4 + 3][mLoad] = v.w;
        __syncthreads();
#pragma unroll
        for (int kk = 0; kk < KT; kk++) {
            float4 xv = *(const float4*)&Xs[kk][ty * 4];
            float wv[VN];
#pragma unroll
            for (int j = 0; j < VN; j++) wv[j] = Wsm[kb + kk][tx * VN + j];
#pragma unroll
            for (int j = 0; j < VN; j++) {
                acc[0][j] += xv.x * wv[j];
                acc[1][j] += xv.y * wv[j];
                acc[2][j] += xv.z * wv[j];
                acc[3][j] += xv.w * wv[j];
            }
        }
    }

#pragma unroll
    for (int i = 0; i < 4; i++) {
        int m = mB + ty * 4 + i;
        if (m < NN) {
#pragma unroll
            for (int j = 0; j < VN; j++) {
                int o = oB + tx * VN + j;
                float vv = acc[i][j] + (BIAS ? __ldg(b + o) : 0.f);
                out[(size_t)m * OUT + o] = RELU ? fmaxf(vv, 0.f) : vv;
            }
        }
    }
}

// ---------------- launch ----------------------------------------------------
static inline int ceil_div(int a, int b) { return (a + b - 1) / b; }

extern "C" void kernel_launch(void* const* d_in, const int* in_sizes, int n_in,
                              void* d_out, int out_size) {
    const float* x  = (const float*)d_in[0];
    const int*   ei = (const int*)d_in[1];   // int32 edge_index (2, E)
    const float* W1 = (const float*)d_in[2]; const float* b1 = (const float*)d_in[3];
    const float* W2 = (const float*)d_in[4]; const float* b2 = (const float*)d_in[5];
    const float* W3 = (const float*)d_in[6]; const float* b3 = (const float*)d_in[7];
    const float* W4 = (const float*)d_in[8]; const float* b4 = (const float*)d_in[9];
    float* out = (float*)d_out;

    const int TB = 256;
    const int gN  = ceil_div(NN, TB);
    const int gE  = ceil_div(EE, TB);
    const int gET = ceil_div(ET, TB);
    const int gW  = ceil_div(NN, TB / 32);   // one warp per node
    const int gM  = ceil_div(NN, 64);        // gemm node-blocks (782)

    // graph prep
    k_zero<<<gN, TB>>>();
    k_count<<<gE, TB>>>(ei);
    k_scan1<<<NB, SB>>>();
    k_scan2<<<1, 128>>>();
    k_scan3<<<NB, SB>>>();
    k_fillself<<<gET, TB>>>(ei);

    // layer 1: h1 = relu((A x) W1 + b1)   — aggregate 29 feats, then GEMM
    k_agg<29, false, X_, A_><<<gW, TB>>>(x, nullptr, nullptr);
    k_gemm_t<29, 96, 2, true, true, A_, B_><<<dim3(gM, 2), TB>>>(nullptr, W1, b1, nullptr);

    // layer 2: h2 = (A h1) W2 + b2       — aggregate 96 feats, then GEMM
    k_agg4<96, false, B_, A_><<<gW, TB>>>(nullptr, nullptr, nullptr);
    k_gemm_t<96, 128, 2, true, false, A_, B_><<<dim3(gM, 2), TB>>>(nullptr, W2, b2, nullptr);

    // layer 3: h3 = A (h2 W3) + b3       — GEMM first (64 < 128), agg with bias
    k_gemm_t<128, 64, 1, false, false, B_, A_><<<dim3(gM, 1), TB>>>(nullptr, W3, nullptr, nullptr);
    k_agg4<64, true, A_, B_><<<gW, TB>>>(nullptr, b3, nullptr);

    // layer 4: out = A (h3 W4) + b4      — GEMM first (32 < 64), agg with bias
    k_gemm_t<64, 32, 1, false, false, B_, A_><<<dim3(gM, 1), TB>>>(nullptr, W4, nullptr, nullptr);
    k_agg4<32, true, A_, X_><<<gW, TB>>>(nullptr, b4, out);

    (void)in_sizes; (void)n_in; (void)out_size;
}

// round 13
// speedup vs baseline: 1.0669x; 1.0163x over previous
#include <cuda_runtime.h>

#define NN 50000
#define EE 800000
#define ET 850000   // EE + NN self-loops
#define SB 512      // scan block size
#define NB ((NN + SB - 1) / SB)   // 98 scan blocks

// ---------------- scratch (device globals; no runtime allocation) ----------
__device__ int   g_deg[NN];
__device__ int   g_cur[NN];
__device__ int   g_off[NN + 1];
__device__ float g_dis[NN];
__device__ int   g_part[NB];
__device__ int   g_pscan[NB];
__device__ int2  g_srcw[ET];            // (src index, weight bits) packed
__device__ float g_bufA[(size_t)NN * 128];
__device__ float g_bufB[(size_t)NN * 128];

// Compile-time buffer selector (no host-side symbol lookup).
enum Which { A_, B_, X_ };
template <Which W>
__device__ __forceinline__ const float* inbuf(const float* ext) {
    if constexpr (W == A_) return g_bufA;
    else if constexpr (W == B_) return g_bufB;
    else return ext;
}
template <Which W>
__device__ __forceinline__ float* outbuf(float* ext) {
    if constexpr (W == A_) return g_bufA;
    else if constexpr (W == B_) return g_bufB;
    else return ext;
}

// ---------------- graph prep ------------------------------------------------
// NOTE: no k_zero — __device__ globals start zeroed at module load, and the
// layer-1 aggregation kernel re-zeros g_deg/g_cur for the next graph replay.

// edge_index is int32 (JAX x64 disabled). Count-only pass.
__global__ void k_count(const int* __restrict__ ei) {
    int e = blockIdx.x * blockDim.x + threadIdx.x;
    if (e >= EE) return;
    int c = ei[EE + e];
    if ((unsigned)c >= NN) c = 0;   // never trap on bad data
    atomicAdd(&g_deg[c], 1);
}

// phase 1: per-block sums of (deg[i]+1)
__global__ __launch_bounds__(SB) void k_scan1() {
    __shared__ int s[SB];
    int t = threadIdx.x;
    int i = blockIdx.x * SB + t;
    s[t] = (i < NN) ? (g_deg[i] + 1) : 0;
    __syncthreads();
#pragma unroll
    for (int o = SB / 2; o > 0; o >>= 1) {
        if (t < o) s[t] += s[t + o];
        __syncthreads();
    }
    if (t == 0) g_part[blockIdx.x] = s[0];
}

// phase 2: exclusive scan of the NB partials (single block of 128)
__global__ __launch_bounds__(128) void k_scan2() {
    __shared__ int s[128];
    int t = threadIdx.x;
    int v = (t < NB) ? g_part[t] : 0;
    s[t] = v;
    __syncthreads();
#pragma unroll
    for (int o = 1; o < 128; o <<= 1) {
        int u = (t >= o) ? s[t - o] : 0;
        __syncthreads();
        s[t] += u;
        __syncthreads();
    }
    if (t < NB) g_pscan[t] = s[t] - v;
    if (t == 0) g_off[NN] = ET;   // total is a compile-time constant
}

// phase 3: block-local exclusive scan + base, write g_off and g_dis
__global__ __launch_bounds__(SB) void k_scan3() {
    __shared__ int s[SB];
    int t = threadIdx.x;
    int i = blockIdx.x * SB + t;
    int d = (i < NN) ? g_deg[i] : 0;
    int v = (i < NN) ? (d + 1) : 0;
    s[t] = v;
    __syncthreads();
#pragma unroll
    for (int o = 1; o < SB; o <<= 1) {
        int u = (t >= o) ? s[t - o] : 0;
        __syncthreads();
        s[t] += u;
        __syncthreads();
    }
    if (i < NN) {
        g_off[i] = g_pscan[blockIdx.x] + s[t] - v;
        g_dis[i] = rsqrtf((float)(d + 1));
    }
}

// fill CSR: edges (read ei directly) + self loops; one packed 8B store/edge
__global__ void k_fillself(const int* __restrict__ ei) {
    int e = blockIdx.x * blockDim.x + threadIdx.x;
    if (e < EE) {
        int r = ei[e];
        int c = ei[EE + e];
        if ((unsigned)r >= NN) r = 0;
        if ((unsigned)c >= NN) c = 0;
        int p = atomicAdd(&g_cur[c], 1);
        float w = g_dis[r] * g_dis[c];
        g_srcw[g_off[c] + p] = make_int2(r, __float_as_int(w));
    } else if (e < EE + NN) {
        int n = e - EE;
        float d = g_dis[n];
        g_srcw[g_off[n + 1] - 1] = make_int2(n, __float_as_int(d * d));
    }
}

// ---------------- scalar aggregation (F=29) + replay cleanup ----------------
template <int F, bool BIAS, bool CLEAN, Which SRC, Which DST>
__global__ __launch_bounds__(256) void k_agg(const float* __restrict__ ext_in,
                                             const float* __restrict__ b,
                                             float* __restrict__ ext_out) {
    const float* __restrict__ h = inbuf<SRC>(ext_in);
    float* __restrict__ out = outbuf<DST>(ext_out);
    constexpr int NACC = (F + 31) / 32;
    int warp = (blockIdx.x * blockDim.x + threadIdx.x) >> 5;
    int lane = threadIdx.x & 31;
    if (warp >= NN) return;
    int n = warp;
    if (CLEAN && lane == 0) { g_deg[n] = 0; g_cur[n] = 0; }  // for next replay
    int s = g_off[n], e = g_off[n + 1];
    float acc[NACC];
#pragma unroll
    for (int j = 0; j < NACC; j++) acc[j] = 0.f;
    for (int i = s; i < e; i++) {
        int2 sw = g_srcw[i];
        int src = sw.x;
        float w = __int_as_float(sw.y);
        const float* hp = h + (size_t)src * F;
#pragma unroll
        for (int j = 0; j < NACC; j++) {
            int f = lane + 32 * j;
            if (f < F) acc[j] += w * __ldg(hp + f);
        }
    }
    float* op = out + (size_t)n * F;
#pragma unroll
    for (int j = 0; j < NACC; j++) {
        int f = lane + 32 * j;
        if (f < F) op[f] = acc[j] + (BIAS ? b[f] : 0.f);
    }
}

// ---------------- vectorized aggregation (F % 4 == 0) -----------------------
template <int F, bool BIAS, Which SRC, Which DST>
__global__ __launch_bounds__(256) void k_agg4(const float* __restrict__ ext_in,
                                              const float* __restrict__ b,
                                              float* __restrict__ ext_out) {
    static_assert(F % 4 == 0, "F must be divisible by 4");
    constexpr int L = F / 4;     // lanes per edge
    constexpr int G = 32 / L;    // concurrent edges per warp
    const float* __restrict__ h = inbuf<SRC>(ext_in);
    float* __restrict__ out = outbuf<DST>(ext_out);
    int warp = (blockIdx.x * blockDim.x + threadIdx.x) >> 5;
    int lane = threadIdx.x & 31;
    if (warp >= NN) return;
    int g = lane / L;
    int q = lane - g * L;
    int s = g_off[warp], e = g_off[warp + 1];
    float4 acc = make_float4(0.f, 0.f, 0.f, 0.f);
    if (g < G) {
        for (int i = s + g; i < e; i += G) {
            int2 sw = g_srcw[i];
            int   src = sw.x;
            float w   = __int_as_float(sw.y);
            float4 v = __ldg((const float4*)(h + (size_t)src * F) + q);
            acc.x += w * v.x; acc.y += w * v.y;
            acc.z += w * v.z; acc.w += w * v.w;
        }
    }
#pragma unroll
    for (int st = G / 2; st >= 1; st >>= 1) {
        int off = st * L;
        acc.x += __shfl_xor_sync(0xffffffffu, acc.x, off);
        acc.y += __shfl_xor_sync(0xffffffffu, acc.y, off);
        acc.z += __shfl_xor_sync(0xffffffffu, acc.z, off);
        acc.w += __shfl_xor_sync(0xffffffffu, acc.w, off);
    }
    if (g == 0) {
        if (BIAS) {
            float4 bb = __ldg((const float4*)b + q);
            acc.x += bb.x; acc.y += bb.y; acc.z += bb.z; acc.w += bb.w;
        }
        ((float4*)(out + (size_t)warp * F))[q] = acc;
    }
}

// ---------------- tiled GEMM: out[n][o] = bias + sum_k x[n][k]*W[k][o] ------
// 128-node x TN-output tile per 256-thread block; W slice loaded once per
// block. Each thread computes 8 rows x VN cols. Weight inner loads SCALAR
// (R10: wide weight LDS regresses); Xs loads LDS.128 (known good).
template <int IN, int OUT, int NOB, bool BIAS, bool RELU, Which SRC, Which DST>
__global__ __launch_bounds__(256) void k_gemm_t(const float* __restrict__ ext_in,
                                                const float* __restrict__ W,
                                                const float* __restrict__ b,
                                                float* __restrict__ ext_out) {
    constexpr int TN  = OUT / NOB;                 // 48, 64, 64, 32
    constexpr int VN  = TN / 16;                   // 3, 4, 4, 2
    constexpr int KT  = 16;
    constexpr int INP = ((IN + KT - 1) / KT) * KT; // 32, 96, 128, 64
    const float* __restrict__ x = inbuf<SRC>(ext_in);
    float* __restrict__ out = outbuf<DST>(ext_out);

    __shared__ float Xs[KT][128];
    __shared__ float Wsm[INP][TN];

    int t  = threadIdx.x;
    int tx = t & 15, ty = t >> 4;
    int mB = blockIdx.x * 128;
    int oB = blockIdx.y * TN;

    // load W slice into shared (zero-pad k >= IN)
    for (int i = t; i < INP * TN; i += 256) {
        int k = i / TN, o = i % TN;
        Wsm[k][o] = (k < IN) ? W[k * OUT + oB + o] : 0.f;
    }

    float acc[8][VN];
#pragma unroll
    for (int i = 0; i < 8; i++)
#pragma unroll
        for (int j = 0; j < VN; j++) acc[i][j] = 0.f;

    int mLoad = t & 127;           // node staged by this thread
    int c8    = (t >> 7) * 8;      // k-offset within tile: 0 or 8
    const float* xrow = x + (size_t)(mB + mLoad) * IN;
    bool mvalid = (mB + mLoad) < NN;

    for (int kb = 0; kb < INP; kb += KT) {
        float4 v0 = make_float4(0.f, 0.f, 0.f, 0.f);
        float4 v1 = make_float4(0.f, 0.f, 0.f, 0.f);
        if (mvalid) {
            int k0 = kb + c8;
            if constexpr (IN % 4 == 0) {
                v0 = *(const float4*)(xrow + k0);       // rows 16B-aligned
                v1 = *(const float4*)(xrow + k0 + 4);
            } else {
                if (k0 + 0 < IN) v0.x = xrow[k0 + 0];
                if (k0 + 1 < IN) v0.y = xrow[k0 + 1];
                if (k0 + 2 < IN) v0.z = xrow[k0 + 2];
                if (k0 + 3 < IN) v0.w = xrow[k0 + 3];
                if (k0 + 4 < IN) v1.x = xrow[k0 + 4];
                if (k0 + 5 < IN) v1.y = xrow[k0 + 5];
                if (k0 + 6 < IN) v1.z = xrow[k0 + 6];
                if (k0 + 7 < IN) v1.w = xrow[k0 + 7];
            }
        }
        __syncthreads();           // previous tile fully consumed (also orders Wsm)
        Xs[c8 + 0][mLoad] = v0.x;
        Xs[c8 + 1][mLoad] = v0.y;
        Xs[c8 + 2][mLoad] = v0.z;
        Xs[c8 + 3][mLoad] = v0.w;
        Xs[c8 + 4][mLoad] = v1.x;
        Xs[c8 + 5][mLoad] = v1.y;
        Xs[c8 + 6][mLoad] = v1.z;
        Xs[c8 + 7][mLoad] = v1.w;
        __syncthreads();
#pragma unroll
        for (int kk = 0; kk < KT; kk++) {
            float4 xa = *(const float4*)&Xs[kk][ty * 8];
            float4 xb = *(const float4*)&Xs[kk][ty * 8 + 4];
            float wv[VN];
#pragma unroll
            for (int j = 0; j < VN; j++) wv[j] = Wsm[kb + kk][tx * VN + j];
#pragma unroll
            for (int j = 0; j < VN; j++) {
                acc[0][j] += xa.x * wv[j];
                acc[1][j] += xa.y * wv[j];
                acc[2][j] += xa.z * wv[j];
                acc[3][j] += xa.w * wv[j];
                acc[4][j] += xb.x * wv[j];
                acc[5][j] += xb.y * wv[j];
                acc[6][j] += xb.z * wv[j];
                acc[7][j] += xb.w * wv[j];
            }
        }
    }

#pragma unroll
    for (int i = 0; i < 8; i++) {
        int m = mB + ty * 8 + i;
        if (m < NN) {
#pragma unroll
            for (int j = 0; j < VN; j++) {
                int o = oB + tx * VN + j;
                float vv = acc[i][j] + (BIAS ? __ldg(b + o) : 0.f);
                out[(size_t)m * OUT + o] = RELU ? fmaxf(vv, 0.f) : vv;
            }
        }
    }
}

// ---------------- launch ----------------------------------------------------
static inline int ceil_div(int a, int b) { return (a + b - 1) / b; }

extern "C" void kernel_launch(void* const* d_in, const int* in_sizes, int n_in,
                              void* d_out, int out_size) {
    const float* x  = (const float*)d_in[0];
    const int*   ei = (const int*)d_in[1];   // int32 edge_index (2, E)
    const float* W1 = (const float*)d_in[2]; const float* b1 = (const float*)d_in[3];
    const float* W2 = (const float*)d_in[4]; const float* b2 = (const float*)d_in[5];
    const float* W3 = (const float*)d_in[6]; const float* b3 = (const float*)d_in[7];
    const float* W4 = (const float*)d_in[8]; const float* b4 = (const float*)d_in[9];
    float* out = (float*)d_out;

    const int TB = 256;
    const int gE  = ceil_div(EE, TB);
    const int gET = ceil_div(ET, TB);
    const int gW  = ceil_div(NN, TB / 32);   // one warp per node
    const int gM  = ceil_div(NN, 128);       // gemm node-blocks (391)

    // graph prep (g_deg/g_cur are zero: module init on call 1, layer-1 agg after)
    k_count<<<gE, TB>>>(ei);
    k_scan1<<<NB, SB>>>();
    k_scan2<<<1, 128>>>();
    k_scan3<<<NB, SB>>>();
    k_fillself<<<gET, TB>>>(ei);

    // layer 1: h1 = relu((A x) W1 + b1)   — aggregate 29 feats, then GEMM
    k_agg<29, false, true, X_, A_><<<gW, TB>>>(x, nullptr, nullptr);
    k_gemm_t<29, 96, 2, true, true, A_, B_><<<dim3(gM, 2), TB>>>(nullptr, W1, b1, nullptr);

    // layer 2: h2 = (A h1) W2 + b2       — aggregate 96 feats, then GEMM
    k_agg4<96, false, B_, A_><<<gW, TB>>>(nullptr, nullptr, nullptr);
    k_gemm_t<96, 128, 2, true, false, A_, B_><<<dim3(gM, 2), TB>>>(nullptr, W2, b2, nullptr);

    // layer 3: h3 = A (h2 W3) + b3       — GEMM first (64 < 128), agg with bias
    k_gemm_t<128, 64, 1, false, false, B_, A_><<<dim3(gM, 1), TB>>>(nullptr, W3, nullptr, nullptr);
    k_agg4<64, true, A_, B_><<<gW, TB>>>(nullptr, b3, nullptr);

    // layer 4: out = A (h3 W4) + b4      — GEMM first (32 < 64), agg with bias
    k_gemm_t<64, 32, 1, false, false, B_, A_><<<dim3(gM, 1), TB>>>(nullptr, W4, nullptr, nullptr);
    k_agg4<32, true, A_, X_><<<gW, TB>>>(nullptr, b4, out);

    (void)in_sizes; (void)n_in; (void)out_size;
}

// round 14
// speedup vs baseline: 1.6364x; 1.5338x over previous
#include <cuda_runtime.h>

#define NN 50000
#define EE 800000
#define ET 850000   // EE + NN self-loops
#define SB 512      // scan block size
#define NB ((NN + SB - 1) / SB)   // 98 scan blocks

// ---------------- scratch (device globals; no runtime allocation) ----------
__device__ int   g_deg[NN];
__device__ int   g_cur[NN];
__device__ int   g_off[NN + 1];
__device__ float g_dis[NN];
__device__ int   g_part[NB];
__device__ int   g_pscan[NB];
__device__ int2  g_srcw[ET];            // (src index, weight bits) packed
__device__ float g_s[NN];               // A·1
__device__ float g_s2[NN];              // A²·1
__device__ float g_T[128 * 32];         // W3·W4
__device__ float g_C[96 * 32];          // W2·W3·W4
__device__ float g_v2[32];              // b2·W3·W4
__device__ float g_v3[32];              // b3·W4
__device__ float g_bufA[(size_t)NN * 128];
__device__ float g_bufB[(size_t)NN * 128];

// Compile-time buffer selector (no host-side symbol lookup).
enum Which { A_, B_, X_ };
template <Which W>
__device__ __forceinline__ const float* inbuf(const float* ext) {
    if constexpr (W == A_) return g_bufA;
    else if constexpr (W == B_) return g_bufB;
    else return ext;
}
template <Which W>
__device__ __forceinline__ float* outbuf(float* ext) {
    if constexpr (W == A_) return g_bufA;
    else if constexpr (W == B_) return g_bufB;
    else return ext;
}

// ---------------- graph prep ------------------------------------------------
// edge_index is int32 (JAX x64 disabled). Count-only pass.
__global__ void k_count(const int* __restrict__ ei) {
    int e = blockIdx.x * blockDim.x + threadIdx.x;
    if (e >= EE) return;
    int c = ei[EE + e];
    if ((unsigned)c >= NN) c = 0;   // never trap on bad data
    atomicAdd(&g_deg[c], 1);
}

__global__ __launch_bounds__(SB) void k_scan1() {
    __shared__ int s[SB];
    int t = threadIdx.x;
    int i = blockIdx.x * SB + t;
    s[t] = (i < NN) ? (g_deg[i] + 1) : 0;
    __syncthreads();
#pragma unroll
    for (int o = SB / 2; o > 0; o >>= 1) {
        if (t < o) s[t] += s[t + o];
        __syncthreads();
    }
    if (t == 0) g_part[blockIdx.x] = s[0];
}

__global__ __launch_bounds__(128) void k_scan2() {
    __shared__ int s[128];
    int t = threadIdx.x;
    int v = (t < NB) ? g_part[t] : 0;
    s[t] = v;
    __syncthreads();
#pragma unroll
    for (int o = 1; o < 128; o <<= 1) {
        int u = (t >= o) ? s[t - o] : 0;
        __syncthreads();
        s[t] += u;
        __syncthreads();
    }
    if (t < NB) g_pscan[t] = s[t] - v;
    if (t == 0) g_off[NN] = ET;
}

__global__ __launch_bounds__(SB) void k_scan3() {
    __shared__ int s[SB];
    int t = threadIdx.x;
    int i = blockIdx.x * SB + t;
    int d = (i < NN) ? g_deg[i] : 0;
    int v = (i < NN) ? (d + 1) : 0;
    s[t] = v;
    __syncthreads();
#pragma unroll
    for (int o = 1; o < SB; o <<= 1) {
        int u = (t >= o) ? s[t - o] : 0;
        __syncthreads();
        s[t] += u;
        __syncthreads();
    }
    if (i < NN) {
        g_off[i] = g_pscan[blockIdx.x] + s[t] - v;
        g_dis[i] = rsqrtf((float)(d + 1));
    }
}

// fill CSR: edges (read ei directly) + self loops; one packed 8B store/edge
__global__ void k_fillself(const int* __restrict__ ei) {
    int e = blockIdx.x * blockDim.x + threadIdx.x;
    if (e < EE) {
        int r = ei[e];
        int c = ei[EE + e];
        if ((unsigned)r >= NN) r = 0;
        if ((unsigned)c >= NN) c = 0;
        int p = atomicAdd(&g_cur[c], 1);
        float w = g_dis[r] * g_dis[c];
        g_srcw[g_off[c] + p] = make_int2(r, __float_as_int(w));
    } else if (e < EE + NN) {
        int n = e - EE;
        float d = g_dis[n];
        g_srcw[g_off[n + 1] - 1] = make_int2(n, __float_as_int(d * d));
    }
}

// ---------------- weight precompute: T=W3W4, v3=b3W4; C=W2T, v2=b2T --------
__global__ void k_wprep1(const float* __restrict__ W3, const float* __restrict__ W4,
                         const float* __restrict__ b3) {
    int i = blockIdx.x * blockDim.x + threadIdx.x;
    if (i < 128 * 32) {
        int k = i >> 5, o = i & 31;
        float sum = 0.f;
        for (int j = 0; j < 64; j++) sum += W3[k * 64 + j] * W4[j * 32 + o];
        g_T[i] = sum;
    } else if (i < 128 * 32 + 32) {
        int o = i - 128 * 32;
        float sum = 0.f;
        for (int j = 0; j < 64; j++) sum += b3[j] * W4[j * 32 + o];
        g_v3[o] = sum;
    }
}

__global__ void k_wprep2(const float* __restrict__ W2, const float* __restrict__ b2) {
    int i = blockIdx.x * blockDim.x + threadIdx.x;
    if (i < 96 * 32) {
        int k = i >> 5, o = i & 31;
        float sum = 0.f;
        for (int j = 0; j < 128; j++) sum += W2[k * 128 + j] * g_T[j * 32 + o];
        g_C[i] = sum;
    } else if (i < 96 * 32 + 32) {
        int o = i - 96 * 32;
        float sum = 0.f;
        for (int j = 0; j < 128; j++) sum += b2[j] * g_T[j * 32 + o];
        g_v2[o] = sum;
    }
}

// ---------------- scalar aggregation (F=29) + replay cleanup ----------------
template <int F, bool BIAS, bool CLEAN, Which SRC, Which DST>
__global__ __launch_bounds__(256) void k_agg(const float* __restrict__ ext_in,
                                             const float* __restrict__ b,
                                             float* __restrict__ ext_out) {
    const float* __restrict__ h = inbuf<SRC>(ext_in);
    float* __restrict__ out = outbuf<DST>(ext_out);
    constexpr int NACC = (F + 31) / 32;
    int warp = (blockIdx.x * blockDim.x + threadIdx.x) >> 5;
    int lane = threadIdx.x & 31;
    if (warp >= NN) return;
    int n = warp;
    if (CLEAN && lane == 0) { g_deg[n] = 0; g_cur[n] = 0; }  // for next replay
    int s = g_off[n], e = g_off[n + 1];
    float acc[NACC];
#pragma unroll
    for (int j = 0; j < NACC; j++) acc[j] = 0.f;
    for (int i = s; i < e; i++) {
        int2 sw = g_srcw[i];
        int src = sw.x;
        float w = __int_as_float(sw.y);
        const float* hp = h + (size_t)src * F;
#pragma unroll
        for (int j = 0; j < NACC; j++) {
            int f = lane + 32 * j;
            if (f < F) acc[j] += w * __ldg(hp + f);
        }
    }
    float* op = out + (size_t)n * F;
#pragma unroll
    for (int j = 0; j < NACC; j++) {
        int f = lane + 32 * j;
        if (f < F) op[f] = acc[j] + (BIAS ? b[f] : 0.f);
    }
}

// ---------------- 32-wide aggregation passes of the collapsed layers --------
// MODE 1: t = A·u,  also s  = A·1   (Σw per node)
// MODE 2: t = A·t1, also s2 = A·s   (Σ w·s[src])
// MODE 3: t = A·t2, epilogue out = t + s2·v2 + s·v3 + b4
template <int MODE, Which SRC, Which DST>
__global__ __launch_bounds__(256) void k_agg32(const float* __restrict__ ext_in,
                                               const float* __restrict__ b4,
                                               float* __restrict__ ext_out) {
    const float* __restrict__ h = inbuf<SRC>(ext_in);
    float* __restrict__ out = outbuf<DST>(ext_out);
    int warp = (blockIdx.x * blockDim.x + threadIdx.x) >> 5;
    int lane = threadIdx.x & 31;
    if (warp >= NN) return;
    int g = lane >> 3;       // 4 edge-groups of 8 lanes
    int q = lane & 7;        // float4 index within the 32-float row
    int s0 = g_off[warp], e0 = g_off[warp + 1];
    float4 acc = make_float4(0.f, 0.f, 0.f, 0.f);
    float ws = 0.f;
    for (int i = s0 + g; i < e0; i += 4) {
        int2 sw = g_srcw[i];
        float w = __int_as_float(sw.y);
        float4 v = __ldg((const float4*)(h + (size_t)sw.x * 32) + q);
        acc.x += w * v.x; acc.y += w * v.y;
        acc.z += w * v.z; acc.w += w * v.w;
        if constexpr (MODE == 1) ws += w;
        if constexpr (MODE == 2) ws += w * __ldg(&g_s[sw.x]);
    }
    // combine the 4 groups (xor 8, 16)
#pragma unroll
    for (int off = 8; off <= 16; off <<= 1) {
        acc.x += __shfl_xor_sync(0xffffffffu, acc.x, off);
        acc.y += __shfl_xor_sync(0xffffffffu, acc.y, off);
        acc.z += __shfl_xor_sync(0xffffffffu, acc.z, off);
        acc.w += __shfl_xor_sync(0xffffffffu, acc.w, off);
        if constexpr (MODE == 1 || MODE == 2)
            ws += __shfl_xor_sync(0xffffffffu, ws, off);
    }
    if constexpr (MODE == 1) { if (lane == 0) g_s[warp] = ws; }
    if constexpr (MODE == 2) { if (lane == 0) g_s2[warp] = ws; }
    if (g == 0) {
        if constexpr (MODE == 3) {
            float ss = g_s[warp], ss2 = g_s2[warp];
            float4 v2q = *(const float4*)&g_v2[q * 4];
            float4 v3q = *(const float4*)&g_v3[q * 4];
            float4 b4q = __ldg((const float4*)b4 + q);
            acc.x += ss2 * v2q.x + ss * v3q.x + b4q.x;
            acc.y += ss2 * v2q.y + ss * v3q.y + b4q.y;
            acc.z += ss2 * v2q.z + ss * v3q.z + b4q.z;
            acc.w += ss2 * v2q.w + ss * v3q.w + b4q.w;
        }
        ((float4*)(out + (size_t)warp * 32))[q] = acc;
    }
}

// ---------------- tiled GEMM: out[n][o] = bias + sum_k x[n][k]*W[k][o] ------
// 128-node x TN-output tile per 256-thread block; W slice loaded once per
// block. Weight inner loads SCALAR (R10: wide weight LDS regresses).
// WFC selects g_C (device-global precomputed W2W3W4) as the weight source.
template <int IN, int OUT, int NOB, bool BIAS, bool RELU, bool WFC, Which SRC, Which DST>
__global__ __launch_bounds__(256) void k_gemm_t(const float* __restrict__ ext_in,
                                                const float* __restrict__ W,
                                                const float* __restrict__ b,
                                                float* __restrict__ ext_out) {
    constexpr int TN  = OUT / NOB;
    constexpr int VN  = TN / 16;
    constexpr int KT  = 16;
    constexpr int INP = ((IN + KT - 1) / KT) * KT;
    const float* __restrict__ x = inbuf<SRC>(ext_in);
    const float* __restrict__ Wp = WFC ? (const float*)g_C : W;
    float* __restrict__ out = outbuf<DST>(ext_out);

    __shared__ float Xs[KT][128];
    __shared__ float Wsm[INP][TN];

    int t  = threadIdx.x;
    int tx = t & 15, ty = t >> 4;
    int mB = blockIdx.x * 128;
    int oB = blockIdx.y * TN;

    for (int i = t; i < INP * TN; i += 256) {
        int k = i / TN, o = i % TN;
        Wsm[k][o] = (k < IN) ? Wp[k * OUT + oB + o] : 0.f;
    }

    float acc[8][VN];
#pragma unroll
    for (int i = 0; i < 8; i++)
#pragma unroll
        for (int j = 0; j < VN; j++) acc[i][j] = 0.f;

    int mLoad = t & 127;
    int c8    = (t >> 7) * 8;
    const float* xrow = x + (size_t)(mB + mLoad) * IN;
    bool mvalid = (mB + mLoad) < NN;

    for (int kb = 0; kb < INP; kb += KT) {
        float4 v0 = make_float4(0.f, 0.f, 0.f, 0.f);
        float4 v1 = make_float4(0.f, 0.f, 0.f, 0.f);
        if (mvalid) {
            int k0 = kb + c8;
            if constexpr (IN % 4 == 0) {
                v0 = *(const float4*)(xrow + k0);
                v1 = *(const float4*)(xrow + k0 + 4);
            } else {
                if (k0 + 0 < IN) v0.x = xrow[k0 + 0];
                if (k0 + 1 < IN) v0.y = xrow[k0 + 1];
                if (k0 + 2 < IN) v0.z = xrow[k0 + 2];
                if (k0 + 3 < IN) v0.w = xrow[k0 + 3];
                if (k0 + 4 < IN) v1.x = xrow[k0 + 4];
                if (k0 + 5 < IN) v1.y = xrow[k0 + 5];
                if (k0 + 6 < IN) v1.z = xrow[k0 + 6];
                if (k0 + 7 < IN) v1.w = xrow[k0 + 7];
            }
        }
        __syncthreads();
        Xs[c8 + 0][mLoad] = v0.x;
        Xs[c8 + 1][mLoad] = v0.y;
        Xs[c8 + 2][mLoad] = v0.z;
        Xs[c8 + 3][mLoad] = v0.w;
        Xs[c8 + 4][mLoad] = v1.x;
        Xs[c8 + 5][mLoad] = v1.y;
        Xs[c8 + 6][mLoad] = v1.z;
        Xs[c8 + 7][mLoad] = v1.w;
        __syncthreads();
#pragma unroll
        for (int kk = 0; kk < KT; kk++) {
            float4 xa = *(const float4*)&Xs[kk][ty * 8];
            float4 xb = *(const float4*)&Xs[kk][ty * 8 + 4];
            float wv[VN];
#pragma unroll
            for (int j = 0; j < VN; j++) wv[j] = Wsm[kb + kk][tx * VN + j];
#pragma unroll
            for (int j = 0; j < VN; j++) {
                acc[0][j] += xa.x * wv[j];
                acc[1][j] += xa.y * wv[j];
                acc[2][j] += xa.z * wv[j];
                acc[3][j] += xa.w * wv[j];
                acc[4][j] += xb.x * wv[j];
                acc[5][j] += xb.y * wv[j];
                acc[6][j] += xb.z * wv[j];
                acc[7][j] += xb.w * wv[j];
            }
        }
    }

#pragma unroll
    for (int i = 0; i < 8; i++) {
        int m = mB + ty * 8 + i;
        if (m < NN) {
#pragma unroll
            for (int j = 0; j < VN; j++) {
                int o = oB + tx * VN + j;
                float vv = acc[i][j] + (BIAS ? __ldg(b + o) : 0.f);
                out[(size_t)m * OUT + o] = RELU ? fmaxf(vv, 0.f) : vv;
            }
        }
    }
}

// ---------------- launch ----------------------------------------------------
static inline int ceil_div(int a, int b) { return (a + b - 1) / b; }

extern "C" void kernel_launch(void* const* d_in, const int* in_sizes, int n_in,
                              void* d_out, int out_size) {
    const float* x  = (const float*)d_in[0];
    const int*   ei = (const int*)d_in[1];   // int32 edge_index (2, E)
    const float* W1 = (const float*)d_in[2]; const float* b1 = (const float*)d_in[3];
    const float* W2 = (const float*)d_in[4]; const float* b2 = (const float*)d_in[5];
    const float* W3 = (const float*)d_in[6]; const float* b3 = (const float*)d_in[7];
    const float* W4 = (const float*)d_in[8]; const float* b4 = (const float*)d_in[9];
    float* out = (float*)d_out;

    const int TB = 256;
    const int gE  = ceil_div(EE, TB);
    const int gET = ceil_div(ET, TB);
    const int gW  = ceil_div(NN, TB / 32);   // one warp per node
    const int gM  = ceil_div(NN, 128);       // gemm node-blocks (391)

    // weight precompute (graph-independent)
    k_wprep1<<<ceil_div(128 * 32 + 32, TB), TB>>>(W3, W4, b3);
    k_wprep2<<<ceil_div(96 * 32 + 32, TB), TB>>>(W2, b2);

    // graph prep (g_deg/g_cur zero: module init on call 1, layer-1 agg after)
    k_count<<<gE, TB>>>(ei);
    k_scan1<<<NB, SB>>>();
    k_scan2<<<1, 128>>>();
    k_scan3<<<NB, SB>>>();
    k_fillself<<<gET, TB>>>(ei);

    // layer 1: h1 = relu((A x) W1 + b1)
    k_agg<29, false, true, X_, A_><<<gW, TB>>>(x, nullptr, nullptr);
    k_gemm_t<29, 96, 2, true, true, false, A_, B_>
        <<<dim3(gM, 2), TB>>>(nullptr, W1, b1, nullptr);

    // collapsed layers 2-4:
    // u = h1·C ; t = A u (+s) ; t = A t (+s2) ; out = A t + s2·v2 + s·v3 + b4
    k_gemm_t<96, 32, 1, false, false, true, B_, A_>
        <<<dim3(gM, 1), TB>>>(nullptr, nullptr, nullptr, nullptr);
    k_agg32<1, A_, B_><<<gW, TB>>>(nullptr, nullptr, nullptr);
    k_agg32<2, B_, A_><<<gW, TB>>>(nullptr, nullptr, nullptr);
    k_agg32<3, A_, X_><<<gW, TB>>>(nullptr, b4, out);

    (void)in_sizes; (void)n_in; (void)out_size;
}